// round 1
// baseline (speedup 1.0000x reference)
#include <cuda_runtime.h>
#include <cstdint>

// Problem constants
#define N_ROWS 8192
#define D_DIM  64
#define B_HALF 1024          // exploit epsilon = [tmp; -tmp] antisymmetry
#define TWO_PI 6.283185307179586f

// Tiling
#define TB 128               // threads per block == rows per block
#define NG 16                // split of the b dimension across blocks
#define BC (B_HALF / NG)     // 64 basis rows per block

typedef unsigned long long u64;

// Packed f32x2 math (Blackwell FFMA2 — 2x fp32 throughput per instruction)
#define FMA2(d, a, b, c) asm("fma.rn.f32x2 %0, %1, %2, %3;" : "=l"(d) : "l"(a), "l"(b), "l"(c))
#define ADD2(d, a, b)    asm("add.rn.f32x2 %0, %1, %2;"     : "=l"(d) : "l"(a), "l"(b))
#define PACK2(d, lo, hi) asm("mov.b64 %0, {%1, %2};"        : "=l"(d) : "f"(lo), "f"(hi))
#define UNPACK2(lo, hi, s) asm("mov.b64 {%0, %1}, %2;"      : "=f"(lo), "=f"(hi) : "l"(s))

// Scratch (static device allocation is the sanctioned workaround)
__device__ float g_S[B_HALF * D_DIM];     // s[b][j] = eps[b][j] / (2*pi*lam[j])
__device__ float g_M[B_HALF * D_DIM];     // mat[b][i]
__device__ float g_ws[B_HALF];            // -(w_s[b] + w_s[b+1024])
__device__ float g_wc[B_HALF];            //  (w_c[b] - w_c[b+1024])
__device__ float g_part[NG * N_ROWS * D_DIM];   // 32 MB partials

// ---------------------------------------------------------------------------
// Precompute S, mat, effective weights. 1024*64 = 65536 threads.
// ---------------------------------------------------------------------------
__global__ void prep_kernel(const float* __restrict__ eps,
                            const float* __restrict__ lam,
                            const float* __restrict__ eta,
                            const float* __restrict__ w) {
    int idx = blockIdx.x * blockDim.x + threadIdx.x;
    if (idx < B_HALF * D_DIM) {
        int b = idx >> 6;
        int j = idx & 63;
        float l = lam[j];
        g_S[idx] = eps[idx] / (TWO_PI * l);
        float eta2 = eta[0] * eta[0];
        float m;
        if (j < 32) {
            // mat[b][i<32] = eps[b][32+i] / lam[32+i]
            m = eps[b * 64 + 32 + j] / lam[32 + j];
        } else {
            // mat[b][i>=32] = -eps[b][i-32]/lam[i-32] - eta^2 * eps[b][i]/lam[i]
            m = -eps[b * 64 + (j - 32)] / lam[j - 32] - eta2 * eps[idx] / l;
        }
        g_M[idx] = m;
    }
    if (idx < B_HALF) {
        g_ws[idx] = -(w[idx] + w[idx + B_HALF]);
        g_wc[idx] = w[2 * B_HALF + idx] - w[3 * B_HALF + idx];
    }
}

// ---------------------------------------------------------------------------
// Main fused kernel. Block = (row tile of 128, b-group of 64).
// Each thread owns one row: x in 32 packed regs, acc in 32 packed regs.
// ---------------------------------------------------------------------------
__global__ void __launch_bounds__(TB, 3)
main_kernel(const float* __restrict__ x) {
    __shared__ __align__(16) float sS[BC * D_DIM];
    __shared__ __align__(16) float sM[BC * D_DIM];
    __shared__ float sW[2 * BC];

    const int tid = threadIdx.x;
    const int row = blockIdx.x * TB + tid;
    const int g   = blockIdx.y;
    const int b0  = g * BC;

    // Stage S / mat tiles into shared memory (vectorized, coalesced)
    {
        const float4* gS4 = reinterpret_cast<const float4*>(g_S + b0 * D_DIM);
        const float4* gM4 = reinterpret_cast<const float4*>(g_M + b0 * D_DIM);
        float4* sS4 = reinterpret_cast<float4*>(sS);
        float4* sM4 = reinterpret_cast<float4*>(sM);
        #pragma unroll
        for (int i = tid; i < BC * (D_DIM / 4); i += TB) {
            sS4[i] = gS4[i];
            sM4[i] = gM4[i];
        }
        if (tid < BC) {
            sW[2 * tid]     = g_ws[b0 + tid];
            sW[2 * tid + 1] = g_wc[b0 + tid];
        }
    }

    // Load this thread's x row into packed registers (32 x f32x2)
    u64 x2[32];
    {
        const u64* xr = reinterpret_cast<const u64*>(x + (size_t)row * D_DIM);
        #pragma unroll
        for (int k = 0; k < 32; ++k) x2[k] = xr[k];
    }

    u64 acc2[32];
    #pragma unroll
    for (int k = 0; k < 32; ++k) acc2[k] = 0ull;   // (0.0f, 0.0f)

    __syncthreads();

    const u64* sSu = reinterpret_cast<const u64*>(sS);
    const u64* sMu = reinterpret_cast<const u64*>(sM);

    #pragma unroll 1
    for (int bb = 0; bb < BC; ++bb) {
        const u64* Sr = sSu + bb * 32;
        // p = x . s_b   (4 independent packed chains for ILP)
        u64 p0 = 0ull, p1 = 0ull, p2 = 0ull, p3 = 0ull;
        #pragma unroll
        for (int k = 0; k < 32; k += 4) {
            u64 e0 = Sr[k], e1 = Sr[k + 1], e2 = Sr[k + 2], e3 = Sr[k + 3];
            FMA2(p0, x2[k],     e0, p0);
            FMA2(p1, x2[k + 1], e1, p1);
            FMA2(p2, x2[k + 2], e2, p2);
            FMA2(p3, x2[k + 3], e3, p3);
        }
        u64 ps, pt;
        ADD2(ps, p0, p1);
        ADD2(pt, p2, p3);
        ADD2(ps, ps, pt);
        float plo, phi;
        UNPACK2(plo, phi, ps);
        float p = plo + phi;            // p = sim / (2*pi)

        // own range reduction -> theta in [-pi, pi] (MUFU sweet spot)
        float r  = p - rintf(p);
        float th = r * TWO_PI;
        float sn = __sinf(th);
        float cs = __cosf(th);
        float u  = sn * sW[2 * bb] + cs * sW[2 * bb + 1];

        u64 u2;
        PACK2(u2, u, u);

        const u64* Mr = sMu + bb * 32;
        #pragma unroll
        for (int k = 0; k < 32; ++k) {
            FMA2(acc2[k], u2, Mr[k], acc2[k]);
        }
    }

    // Store partial result for this b-group
    {
        u64* dst = reinterpret_cast<u64*>(g_part + ((size_t)g * N_ROWS + row) * D_DIM);
        #pragma unroll
        for (int k = 0; k < 32; ++k) dst[k] = acc2[k];
    }
}

// ---------------------------------------------------------------------------
// Reduce the NG partial buffers into the output.
// ---------------------------------------------------------------------------
__global__ void reduce_kernel(float* __restrict__ out) {
    int idx = blockIdx.x * blockDim.x + threadIdx.x;   // < N_ROWS * D_DIM
    float s = 0.0f;
    #pragma unroll
    for (int g = 0; g < NG; ++g) {
        s += g_part[(size_t)g * (N_ROWS * D_DIM) + idx];
    }
    out[idx] = s;
}

// ---------------------------------------------------------------------------
extern "C" void kernel_launch(void* const* d_in, const int* in_sizes, int n_in,
                              void* d_out, int out_size) {
    // Robust input mapping by element count (t and eta are both size 1;
    // t comes first in metadata order, eta second).
    const float* x   = nullptr;
    const float* eps = nullptr;
    const float* lam = nullptr;
    const float* eta = nullptr;
    const float* w   = nullptr;
    int ones_seen = 0;
    for (int i = 0; i < n_in; ++i) {
        int sz = in_sizes[i];
        const float* p = (const float*)d_in[i];
        if      (sz == N_ROWS * D_DIM)     x   = p;
        else if (sz == 2 * B_HALF * D_DIM) eps = p;
        else if (sz == D_DIM)              lam = p;
        else if (sz == 4 * B_HALF)         w   = p;
        else if (sz == 1) {
            if (ones_seen == 1) eta = p;   // second size-1 input is eta
            ones_seen++;
        }
    }

    prep_kernel<<<(B_HALF * D_DIM + 255) / 256, 256>>>(eps, lam, eta, w);
    main_kernel<<<dim3(N_ROWS / TB, NG), TB>>>(x);
    reduce_kernel<<<(N_ROWS * D_DIM + 255) / 256, 256>>>((float*)d_out);
}